// round 9
// baseline (speedup 1.0000x reference)
#include <cuda_runtime.h>
#include <math.h>

#define HH 512
#define WW 512
#define RR 4
#define NIMG 64
#define NEL (NIMG*HH*WW)

// tile geometry: TR=32 -> no row-bound checks (512/32=16)
#define TC 32             // output cols per block
#define TR 32             // output rows per block
#define HR 40             // halo rows
#define HC 40             // halo cols
#define PIN 41            // scalar plane pitch (floats)
#define PIN2 41           // float2 plane pitch (float2s)
#define PH2 33            // h plane pitch (float2s)
#define NTS 512           // k_stats threads
#define NTF 256           // k_final threads
#define GY (HH / TR)      // 16

// Scratch (device globals: no allocation allowed)
__device__ double g_partial[2048];
__device__ float  g_invSf;
__device__ float2 g_AB[NEL];      // interleaved (A, b)

// ---------------- Stage 1: deterministic global sum of |a| + 1e-12 (fp64) ----
__global__ void k_sum_partial(const float* __restrict__ a) {
    __shared__ double wsum[8];
    const int b = blockIdx.x, t = threadIdx.x;
    const float4* p = (const float4*)(a + (size_t)b * 8192);
    double acc = 0.0;
    #pragma unroll
    for (int j = 0; j < 8; j++) {
        float4 v = p[t + j * 256];
        acc += (fabs((double)v.x) + 1e-12) + (fabs((double)v.y) + 1e-12)
             + (fabs((double)v.z) + 1e-12) + (fabs((double)v.w) + 1e-12);
    }
    #pragma unroll
    for (int o = 16; o > 0; o >>= 1) acc += __shfl_down_sync(0xffffffffu, acc, o);
    if ((t & 31) == 0) wsum[t >> 5] = acc;
    __syncthreads();
    if (t == 0) {
        double s = 0.0;
        #pragma unroll
        for (int w = 0; w < 8; w++) s += wsum[w];
        g_partial[b] = s;
    }
}

__global__ void k_sum_final() {
    __shared__ double wsum[8];
    const int t = threadIdx.x;
    double acc = 0.0;
    for (int j = t; j < 2048; j += 256) acc += g_partial[j];
    #pragma unroll
    for (int o = 16; o > 0; o >>= 1) acc += __shfl_down_sync(0xffffffffu, acc, o);
    if ((t & 31) == 0) wsum[t >> 5] = acc;
    __syncthreads();
    if (t == 0) {
        double s = 0.0;
        for (int w = 0; w < 8; w++) s += wsum[w];
        g_invSf = (float)(1.0 / s);
    }
}

// ---------------- Stage 2: fused 6-quantity box filter -> (A,b) ----------------
// 512 threads, 4 blocks/SM -> 64 warps/SM. Phase C uses 2-row runs so all 512
// threads stay active (taps cost accepted: occupancy > bytes on this kernel).
__global__ __launch_bounds__(NTS, 4) void k_stats(
    const float* __restrict__ X, const float* __restrict__ Y,
    const float* __restrict__ Wt)
{
    extern __shared__ unsigned char smem_raw[];
    float2* sXY = (float2*)smem_raw;                 // [HR*PIN2] (x, y)
    float*  sA  = (float*)(sXY + HR * PIN2);         // [HR*PIN]  |a|+eps
    float2* sH0 = (float2*)(sA + HR * PIN);          // (h_a,    h_a2xy)
    float2* sH1 = sH0 + HR * PH2;                    // (h_a2x,  h_ay)
    float2* sH2 = sH1 + HR * PH2;                    // (h_a2x2, h_ax)

    const int tid = threadIdx.x;
    const int img = blockIdx.z;
    const int bc  = blockIdx.x * TC;
    const int br  = blockIdx.y * TR;
    const size_t ibase = (size_t)img * (HH * WW);

    // ---- Phase A: vectorized halo load, single pass (400 items < 512) ----
    if (tid < HR * (HC / 4)) {
        const int rh = tid / (HC / 4);
        const int vq = tid % (HC / 4);
        const int gr = br - RR + rh;
        const int gc = bc - RR + vq * 4;       // multiple of 4, aligned
        float4 xv = make_float4(0.f,0.f,0.f,0.f);
        float4 yv = xv, av = xv;
        if (gr >= 0 && gr < HH && gc >= 0 && gc < WW) {
            const size_t o = ibase + (size_t)gr * WW + gc;
            xv = *(const float4*)(X  + o);
            yv = *(const float4*)(Y  + o);
            av = *(const float4*)(Wt + o);
        }
        const int sb2 = rh * PIN2 + vq * 4;
        sXY[sb2+0] = make_float2(xv.x, yv.x);
        sXY[sb2+1] = make_float2(xv.y, yv.y);
        sXY[sb2+2] = make_float2(xv.z, yv.z);
        sXY[sb2+3] = make_float2(xv.w, yv.w);
        const int sb = rh * PIN + vq * 4;
        sA[sb+0]=fabsf(av.x)+1e-12f; sA[sb+1]=fabsf(av.y)+1e-12f;
        sA[sb+2]=fabsf(av.z)+1e-12f; sA[sb+3]=fabsf(av.w)+1e-12f;
    }
    __syncthreads();

    // ---- Phase B: horizontal 9-tap, 4-col sliding runs; rows 0-31 and
    //      rows 32-39 handled by DIFFERENT warps concurrently ----
    if (tid < 320) {
        int rh, cg;
        if (tid < 256) { rh = tid & 31;        cg = tid >> 5; }          // rows 0..31
        else           { rh = 32 + (tid & 7);  cg = (tid >> 3) & 7; }    // rows 32..39
        const int b2 = rh * PIN2 + cg * 4;
        const int bA = rh * PIN  + cg * 4;
        const int hb = rh * PH2  + cg * 4;

        float h0=0.f,h1=0.f,h2=0.f,h3=0.f,h4=0.f,h5=0.f;
        #pragma unroll
        for (int d = 0; d < 9; ++d) {
            const float2 xy = sXY[b2 + d];
            const float  av = sA [bA + d];
            const float ax = av * xy.x, a2x = ax * av;
            h0 += av; h5 += ax; h2 += a2x;
            h3 = fmaf(av,  xy.y, h3);
            h1 = fmaf(a2x, xy.y, h1);
            h4 = fmaf(a2x, xy.x, h4);
        }
        sH0[hb] = make_float2(h0, h1);
        sH1[hb] = make_float2(h2, h3);
        sH2[hb] = make_float2(h4, h5);

        #pragma unroll
        for (int s = 1; s < 4; ++s) {
            float2 xy = sXY[b2 + 8 + s];
            float  av = sA [bA + 8 + s];
            float ax = av * xy.x, a2x = ax * av;
            h0 += av; h5 += ax; h2 += a2x;
            h3 = fmaf(av,  xy.y, h3);
            h1 = fmaf(a2x, xy.y, h1);
            h4 = fmaf(a2x, xy.x, h4);
            xy = sXY[b2 + s - 1];
            av = sA [bA + s - 1];
            ax = av * xy.x; a2x = ax * av;
            h0 -= av; h5 -= ax; h2 -= a2x;
            h3 = fmaf(-av,  xy.y, h3);
            h1 = fmaf(-a2x, xy.y, h1);
            h4 = fmaf(-a2x, xy.x, h4);
            sH0[hb+s] = make_float2(h0, h1);
            sH1[hb+s] = make_float2(h2, h3);
            sH2[hb+s] = make_float2(h4, h5);
        }
    }
    __syncthreads();

    // ---- Phase C: vertical 9-tap, 2-row runs, ALL 512 threads + solve ----
    {
        const int c   = tid & 31;
        const int seg = tid >> 5;            // 0..15 -> rows seg*2, seg*2+1
        const int col = bc + c;
        const int ncl = min(col + RR, WW - 1) - max(col - RR, 0) + 1;
        const float invS = g_invSf;
        const int r0 = seg * 2;

        float a0=0.f,a1=0.f,a2=0.f,a3=0.f,a4=0.f,a5=0.f;
        #pragma unroll
        for (int d = 0; d < 9; ++d) {
            const int hb = (r0 + d) * PH2 + c;
            const float2 p = sH0[hb], q = sH1[hb], r = sH2[hb];
            a0 += p.x; a1 += p.y; a2 += q.x;
            a3 += q.y; a4 += r.x; a5 += r.y;
        }
        #pragma unroll
        for (int i = 0; i < 2; ++i) {
            const int gro = br + r0 + i;     // always < HH (512 = 16*32)
            {
                const int nr = min(gro + RR, HH - 1) - max(gro - RR, 0) + 1;
                const float Nf  = (float)(nr * ncl);
                const float num = fmaf(-(a2 * a3), invS, a1);
                const float den = fabsf(fmaf(-(a2 * a5), invS, a4)) + Nf * 1e-8f;
                const float Av  = __fdividef(num, den);
                const float bv  = __fdividef(fmaf(-Av, a5, a3), a0);
                g_AB[ibase + (size_t)gro * WW + col] = make_float2(Av, bv);
            }
            if (i < 1) {
                const int ha = (r0 + 9) * PH2 + c;
                const int hs = r0 * PH2 + c;
                const float2 pa = sH0[ha], qa = sH1[ha], ra = sH2[ha];
                const float2 ps = sH0[hs], qs = sH1[hs], rs = sH2[hs];
                a0 += pa.x - ps.x; a1 += pa.y - ps.y;
                a2 += qa.x - qs.x; a3 += qa.y - qs.y;
                a4 += ra.x - rs.x; a5 += ra.y - rs.y;
            }
        }
    }
}

// ---------------- Stage 3: box filter (A,b) + final blend (R8 unchanged) ------
__global__ __launch_bounds__(NTF) void k_final(
    const float* __restrict__ X, float* __restrict__ out)
{
    __shared__ float2 sAB [HR * PIN2];
    __shared__ float2 sHab[HR * PH2];

    const int tid = threadIdx.x;
    const int img = blockIdx.z;
    const int bc  = blockIdx.x * TC;
    const int br  = blockIdx.y * TR;
    const size_t ibase = (size_t)img * (HH * WW);

    // Phase A: float4 = 2 pixels of (A,b); 800 items
    #pragma unroll
    for (int it = 0; it < 4; ++it) {
        const int idx = tid + it * NTF;
        if (idx < HR * (HC / 2)) {
            const int rh = idx / (HC / 2);
            const int vq = idx % (HC / 2);
            const int gr = br - RR + rh;
            const int gc = bc - RR + vq * 2;      // even pixel col
            float4 v = make_float4(0.f,0.f,0.f,0.f);
            if (gr >= 0 && gr < HH && gc >= 0 && gc < WW) {
                const size_t o = ibase + (size_t)gr * WW + gc;
                v = *(const float4*)(g_AB + o);
            }
            const int sb2 = rh * PIN2 + vq * 2;
            sAB[sb2+0] = make_float2(v.x, v.y);
            sAB[sb2+1] = make_float2(v.z, v.w);
        }
    }
    __syncthreads();

    // Phase B: horizontal 9-tap, 4-col runs (rows 0..31 by 256 thr, 32..39 by 64)
    #pragma unroll
    for (int step = 0; step < 2; ++step) {
        int rh, cg;
        bool act;
        if (step == 0) { rh = tid & 31;          cg = tid >> 5; act = true; }
        else           { rh = 32 + (tid & 7);    cg = tid >> 3; act = (tid < 64); }
        if (act) {
            const int b2 = rh * PIN2 + cg * 4;
            const int hb = rh * PH2  + cg * 4;
            float hA = 0.f, hB = 0.f;
            #pragma unroll
            for (int d = 0; d < 9; ++d) {
                const float2 ab = sAB[b2 + d];
                hA += ab.x; hB += ab.y;
            }
            sHab[hb] = make_float2(hA, hB);
            #pragma unroll
            for (int s = 1; s < 4; ++s) {
                const float2 aa = sAB[b2 + 8 + s];
                const float2 as = sAB[b2 + s - 1];
                hA += aa.x - as.x;
                hB += aa.y - as.y;
                sHab[hb + s] = make_float2(hA, hB);
            }
        }
    }
    __syncthreads();

    // Phase C: vertical 9-tap, 4-row runs, all 256 threads + blend
    {
        const int c   = tid & 31;
        const int seg = tid >> 5;
        const int col = bc + c;
        const int ncl = min(col + RR, WW - 1) - max(col - RR, 0) + 1;
        const int r0 = seg * 4;

        float xv[4];
        #pragma unroll
        for (int i = 0; i < 4; ++i)
            xv[i] = X[ibase + (size_t)(br + r0 + i) * WW + col];

        float aA = 0.f, aB = 0.f;
        #pragma unroll
        for (int d = 0; d < 9; ++d) {
            const float2 h = sHab[(r0 + d) * PH2 + c];
            aA += h.x; aB += h.y;
        }
        #pragma unroll
        for (int i = 0; i < 4; ++i) {
            const int gro = br + r0 + i;     // always < HH
            const int nr = min(gro + RR, HH - 1) - max(gro - RR, 0) + 1;
            const float rcpN = __fdividef(1.f, (float)(nr * ncl));
            out[ibase + (size_t)gro * WW + col] = (aA * xv[i] + aB) * rcpN;
            if (i < 3) {
                const float2 ha = sHab[(r0 + 9 + i) * PH2 + c];
                const float2 hs = sHab[(r0 + i) * PH2 + c];
                aA += ha.x - hs.x;
                aB += ha.y - hs.y;
            }
        }
    }
}

extern "C" void kernel_launch(void* const* d_in, const int* in_sizes, int n_in,
                              void* d_out, int out_size) {
    const float* x = (const float*)d_in[0];  // lr_x
    const float* y = (const float*)d_in[1];  // lr_y
    const float* a = (const float*)d_in[2];  // l_a
    float* out = (float*)d_out;

    k_sum_partial<<<2048, 256>>>(a);
    k_sum_final<<<1, 256>>>();

    const int smem_stats = (HR * PIN2 * 2 + HR * PIN + 3 * HR * PH2 * 2) * (int)sizeof(float); // 51360
    cudaFuncSetAttribute(k_stats, cudaFuncAttributeMaxDynamicSharedMemorySize, smem_stats);

    dim3 grid(WW / TC, GY, NIMG);  // 16 x 16 x 64
    k_stats<<<grid, NTS, smem_stats>>>(x, y, a);
    k_final<<<grid, NTF>>>(x, out);
}

// round 10
// speedup vs baseline: 1.0980x; 1.0980x over previous
#include <cuda_runtime.h>
#include <cuda_fp16.h>
#include <math.h>

#define HH 512
#define WW 512
#define RR 4
#define NIMG 64
#define NEL (NIMG*HH*WW)

// tile geometry: TR=32 -> no row-bound checks (512/32=16)
#define TC 32             // output cols per block
#define TR 32             // output rows per block
#define HR 40             // halo rows
#define HC 40             // halo cols
#define PIN 41            // scalar plane pitch (floats)
#define PIN2 41           // float2 plane pitch (float2s)
#define PH2 33            // h plane pitch (elements)
#define NTHR 256
#define GY (HH / TR)      // 16

// Scratch (device globals: no allocation allowed)
__device__ double g_partial[2048];
__device__ float  g_invSf;
__device__ float2 g_AB[NEL];      // interleaved (A, b)

// ---------------- Stage 1: deterministic global sum of |a| + 1e-12 (fp64) ----
__global__ void k_sum_partial(const float* __restrict__ a) {
    __shared__ double wsum[8];
    const int b = blockIdx.x, t = threadIdx.x;
    const float4* p = (const float4*)(a + (size_t)b * 8192);
    double acc = 0.0;
    #pragma unroll
    for (int j = 0; j < 8; j++) {
        float4 v = p[t + j * 256];
        acc += (fabs((double)v.x) + 1e-12) + (fabs((double)v.y) + 1e-12)
             + (fabs((double)v.z) + 1e-12) + (fabs((double)v.w) + 1e-12);
    }
    #pragma unroll
    for (int o = 16; o > 0; o >>= 1) acc += __shfl_down_sync(0xffffffffu, acc, o);
    if ((t & 31) == 0) wsum[t >> 5] = acc;
    __syncthreads();
    if (t == 0) {
        double s = 0.0;
        #pragma unroll
        for (int w = 0; w < 8; w++) s += wsum[w];
        g_partial[b] = s;
    }
}

__global__ void k_sum_final() {
    __shared__ double wsum[8];
    const int t = threadIdx.x;
    double acc = 0.0;
    for (int j = t; j < 2048; j += 256) acc += g_partial[j];
    #pragma unroll
    for (int o = 16; o > 0; o >>= 1) acc += __shfl_down_sync(0xffffffffu, acc, o);
    if ((t & 31) == 0) wsum[t >> 5] = acc;
    __syncthreads();
    if (t == 0) {
        double s = 0.0;
        for (int w = 0; w < 8; w++) s += wsum[w];
        g_invSf = (float)(1.0 / s);
    }
}

// ---------------- Stage 2: fused 6-quantity box filter -> (A,b) ----------------
// R8 structure; h-planes mixed precision: (h1,h4)=fp32 float2 (feed A num/den),
// (h0,h3) and (h2,h5) = half2 (feed b / tiny S-corrections only).
// smem 40.8 KB -> 5 blocks/SM (40 warps), C-reads 24B->16B per tap.
__global__ __launch_bounds__(NTHR) void k_stats(
    const float* __restrict__ X, const float* __restrict__ Y,
    const float* __restrict__ Wt)
{
    extern __shared__ unsigned char smem_raw[];
    float2*  sXY = (float2*)smem_raw;                // [HR*PIN2] (x, y)
    float*   sA  = (float*)(sXY + HR * PIN2);        // [HR*PIN]  |a|+eps
    float2*  sF  = (float2*)(sA + HR * PIN);         // (h1=a2xy, h4=a2x2) fp32
    __half2* sG  = (__half2*)(sF + HR * PH2);        // (h0=a,    h3=ay)   fp16
    __half2* sK  = sG + HR * PH2;                    // (h2=a2x,  h5=ax)   fp16

    const int tid = threadIdx.x;
    const int img = blockIdx.z;
    const int bc  = blockIdx.x * TC;
    const int br  = blockIdx.y * TR;
    const size_t ibase = (size_t)img * (HH * WW);

    // ---- Phase A: vectorized halo load (zero outside = truncated box) ----
    #pragma unroll
    for (int it = 0; it < 2; ++it) {
        const int idx = tid + it * NTHR;
        if (idx < HR * (HC / 4)) {                 // 400 items
            const int rh = idx / (HC / 4);
            const int vq = idx % (HC / 4);
            const int gr = br - RR + rh;
            const int gc = bc - RR + vq * 4;       // multiple of 4, aligned
            float4 xv = make_float4(0.f,0.f,0.f,0.f);
            float4 yv = xv, av = xv;
            if (gr >= 0 && gr < HH && gc >= 0 && gc < WW) {
                const size_t o = ibase + (size_t)gr * WW + gc;
                xv = *(const float4*)(X  + o);
                yv = *(const float4*)(Y  + o);
                av = *(const float4*)(Wt + o);
            }
            const int sb2 = rh * PIN2 + vq * 4;
            sXY[sb2+0] = make_float2(xv.x, yv.x);
            sXY[sb2+1] = make_float2(xv.y, yv.y);
            sXY[sb2+2] = make_float2(xv.z, yv.z);
            sXY[sb2+3] = make_float2(xv.w, yv.w);
            const int sb = rh * PIN + vq * 4;
            sA[sb+0]=fabsf(av.x)+1e-12f; sA[sb+1]=fabsf(av.y)+1e-12f;
            sA[sb+2]=fabsf(av.z)+1e-12f; sA[sb+3]=fabsf(av.w)+1e-12f;
        }
    }
    __syncthreads();

    // ---- Phase B: horizontal 9-tap, sliding over 4 cols per thread ----
    // step 1: rows 0..31 (all 256 threads); step 2: rows 32..39 (64 threads)
    #pragma unroll
    for (int step = 0; step < 2; ++step) {
        int rh, cg;
        bool act;
        if (step == 0) { rh = tid & 31;          cg = tid >> 5; act = true; }
        else           { rh = 32 + (tid & 7);    cg = tid >> 3; act = (tid < 64); }
        if (act) {
            const int b2 = rh * PIN2 + cg * 4;
            const int bA = rh * PIN  + cg * 4;
            const int hb = rh * PH2  + cg * 4;

            float h0=0.f,h1=0.f,h2=0.f,h3=0.f,h4=0.f,h5=0.f;
            #pragma unroll
            for (int d = 0; d < 9; ++d) {
                const float2 xy = sXY[b2 + d];
                const float  av = sA [bA + d];
                const float ax = av * xy.x, a2x = ax * av;
                h0 += av; h5 += ax; h2 += a2x;
                h3 = fmaf(av,  xy.y, h3);
                h1 = fmaf(a2x, xy.y, h1);
                h4 = fmaf(a2x, xy.x, h4);
            }
            sF[hb] = make_float2(h1, h4);
            sG[hb] = __floats2half2_rn(h0, h3);
            sK[hb] = __floats2half2_rn(h2, h5);

            #pragma unroll
            for (int s = 1; s < 4; ++s) {
                float2 xy = sXY[b2 + 8 + s];
                float  av = sA [bA + 8 + s];
                float ax = av * xy.x, a2x = ax * av;
                h0 += av; h5 += ax; h2 += a2x;
                h3 = fmaf(av,  xy.y, h3);
                h1 = fmaf(a2x, xy.y, h1);
                h4 = fmaf(a2x, xy.x, h4);
                xy = sXY[b2 + s - 1];
                av = sA [bA + s - 1];
                ax = av * xy.x; a2x = ax * av;
                h0 -= av; h5 -= ax; h2 -= a2x;
                h3 = fmaf(-av,  xy.y, h3);
                h1 = fmaf(-a2x, xy.y, h1);
                h4 = fmaf(-a2x, xy.x, h4);
                sF[hb+s] = make_float2(h1, h4);
                sG[hb+s] = __floats2half2_rn(h0, h3);
                sK[hb+s] = __floats2half2_rn(h2, h5);
            }
        }
    }
    __syncthreads();

    // ---- Phase C: vertical 9-tap, 4-row runs, all 256 threads + solve ----
    {
        const int c   = tid & 31;
        const int seg = tid >> 5;            // 0..7 -> rows seg*4 ..
        const int col = bc + c;
        const int ncl = min(col + RR, WW - 1) - max(col - RR, 0) + 1;
        const float invS = g_invSf;
        const int r0 = seg * 4;

        float a0=0.f,a1=0.f,a2=0.f,a3=0.f,a4=0.f,a5=0.f;
        #pragma unroll
        for (int d = 0; d < 9; ++d) {
            const int hb = (r0 + d) * PH2 + c;
            const float2 f = sF[hb];
            const float2 g = __half22float2(sG[hb]);
            const float2 k = __half22float2(sK[hb]);
            a1 += f.x; a4 += f.y;
            a0 += g.x; a3 += g.y;
            a2 += k.x; a5 += k.y;
        }
        #pragma unroll
        for (int i = 0; i < 4; ++i) {
            const int gro = br + r0 + i;     // always < HH (512 = 16*32)
            {
                const int nr = min(gro + RR, HH - 1) - max(gro - RR, 0) + 1;
                const float Nf  = (float)(nr * ncl);
                const float num = fmaf(-(a2 * a3), invS, a1);
                const float den = fabsf(fmaf(-(a2 * a5), invS, a4)) + Nf * 1e-8f;
                const float Av  = __fdividef(num, den);
                const float bv  = __fdividef(fmaf(-Av, a5, a3), a0);
                g_AB[ibase + (size_t)gro * WW + col] = make_float2(Av, bv);
            }
            if (i < 3) {
                const int ha = (r0 + 9 + i) * PH2 + c;
                const int hs = (r0 + i) * PH2 + c;
                const float2 fa = sF[ha], fs = sF[hs];
                const float2 ga = __half22float2(sG[ha]), gs = __half22float2(sG[hs]);
                const float2 ka = __half22float2(sK[ha]), ks = __half22float2(sK[hs]);
                a1 += fa.x - fs.x; a4 += fa.y - fs.y;
                a0 += ga.x - gs.x; a3 += ga.y - gs.y;
                a2 += ka.x - ks.x; a5 += ka.y - ks.y;
            }
        }
    }
}

// ---------------- Stage 3: box filter (A,b) + final blend (R8 unchanged) ------
__global__ __launch_bounds__(NTHR) void k_final(
    const float* __restrict__ X, float* __restrict__ out)
{
    __shared__ float2 sAB [HR * PIN2];
    __shared__ float2 sHab[HR * PH2];

    const int tid = threadIdx.x;
    const int img = blockIdx.z;
    const int bc  = blockIdx.x * TC;
    const int br  = blockIdx.y * TR;
    const size_t ibase = (size_t)img * (HH * WW);

    // Phase A: float4 = 2 pixels of (A,b); 800 items
    #pragma unroll
    for (int it = 0; it < 4; ++it) {
        const int idx = tid + it * NTHR;
        if (idx < HR * (HC / 2)) {
            const int rh = idx / (HC / 2);
            const int vq = idx % (HC / 2);
            const int gr = br - RR + rh;
            const int gc = bc - RR + vq * 2;      // even pixel col
            float4 v = make_float4(0.f,0.f,0.f,0.f);
            if (gr >= 0 && gr < HH && gc >= 0 && gc < WW) {
                const size_t o = ibase + (size_t)gr * WW + gc;
                v = *(const float4*)(g_AB + o);
            }
            const int sb2 = rh * PIN2 + vq * 2;
            sAB[sb2+0] = make_float2(v.x, v.y);
            sAB[sb2+1] = make_float2(v.z, v.w);
        }
    }
    __syncthreads();

    // Phase B: horizontal 9-tap, 4-col runs (rows 0..31 by 256 thr, 32..39 by 64)
    #pragma unroll
    for (int step = 0; step < 2; ++step) {
        int rh, cg;
        bool act;
        if (step == 0) { rh = tid & 31;          cg = tid >> 5; act = true; }
        else           { rh = 32 + (tid & 7);    cg = tid >> 3; act = (tid < 64); }
        if (act) {
            const int b2 = rh * PIN2 + cg * 4;
            const int hb = rh * PH2  + cg * 4;
            float hA = 0.f, hB = 0.f;
            #pragma unroll
            for (int d = 0; d < 9; ++d) {
                const float2 ab = sAB[b2 + d];
                hA += ab.x; hB += ab.y;
            }
            sHab[hb] = make_float2(hA, hB);
            #pragma unroll
            for (int s = 1; s < 4; ++s) {
                const float2 aa = sAB[b2 + 8 + s];
                const float2 as = sAB[b2 + s - 1];
                hA += aa.x - as.x;
                hB += aa.y - as.y;
                sHab[hb + s] = make_float2(hA, hB);
            }
        }
    }
    __syncthreads();

    // Phase C: vertical 9-tap, 4-row runs, all 256 threads + blend
    {
        const int c   = tid & 31;
        const int seg = tid >> 5;
        const int col = bc + c;
        const int ncl = min(col + RR, WW - 1) - max(col - RR, 0) + 1;
        const int r0 = seg * 4;

        float xv[4];
        #pragma unroll
        for (int i = 0; i < 4; ++i)
            xv[i] = X[ibase + (size_t)(br + r0 + i) * WW + col];

        float aA = 0.f, aB = 0.f;
        #pragma unroll
        for (int d = 0; d < 9; ++d) {
            const float2 h = sHab[(r0 + d) * PH2 + c];
            aA += h.x; aB += h.y;
        }
        #pragma unroll
        for (int i = 0; i < 4; ++i) {
            const int gro = br + r0 + i;     // always < HH
            const int nr = min(gro + RR, HH - 1) - max(gro - RR, 0) + 1;
            const float rcpN = __fdividef(1.f, (float)(nr * ncl));
            out[ibase + (size_t)gro * WW + col] = (aA * xv[i] + aB) * rcpN;
            if (i < 3) {
                const float2 ha = sHab[(r0 + 9 + i) * PH2 + c];
                const float2 hs = sHab[(r0 + i) * PH2 + c];
                aA += ha.x - hs.x;
                aB += ha.y - hs.y;
            }
        }
    }
}

extern "C" void kernel_launch(void* const* d_in, const int* in_sizes, int n_in,
                              void* d_out, int out_size) {
    const float* x = (const float*)d_in[0];  // lr_x
    const float* y = (const float*)d_in[1];  // lr_y
    const float* a = (const float*)d_in[2];  // l_a
    float* out = (float*)d_out;

    k_sum_partial<<<2048, 256>>>(a);
    k_sum_final<<<1, 256>>>();

    // smem: xy 13120 + a 6560 + F 10560 + G 5280 + K 5280 = 40800 B -> 5 blocks/SM
    const int smem_stats = HR * PIN2 * 8 + HR * PIN * 4
                         + HR * PH2 * 8 + 2 * (HR * PH2 * 4);
    cudaFuncSetAttribute(k_stats, cudaFuncAttributeMaxDynamicSharedMemorySize, smem_stats);

    dim3 grid(WW / TC, GY, NIMG);  // 16 x 16 x 64
    k_stats<<<grid, NTHR, smem_stats>>>(x, y, a);
    k_final<<<grid, NTHR>>>(x, out);
}

// round 11
// speedup vs baseline: 1.1991x; 1.0922x over previous
#include <cuda_runtime.h>
#include <cuda_fp16.h>
#include <math.h>

#define HH 512
#define WW 512
#define RR 4
#define NIMG 64
#define NEL (NIMG*HH*WW)

// tile geometry: TR=32 -> no row-bound checks (512/32=16)
#define TC 32             // output cols per block
#define TR 32             // output rows per block
#define HR 40             // halo rows
#define HC 40             // halo cols
#define PIN2 41           // float2 plane pitch (float2s) -> conflict-free
#define PINH 42           // half plane pitch (halves, 21 words) -> conflict-free
#define PH2 33            // h plane pitch (elements) -> conflict-free
#define PAB 41            // k_final A,b half2 pitch (half2s, 41 words) -> conflict-free
#define NTHR 256
#define GY (HH / TR)      // 16

// Scratch (device globals: no allocation allowed)
__device__ double  g_partial[2048];
__device__ float   g_invSf;
__device__ __half2 g_ABh[NEL];    // interleaved (A, b) in fp16

// ---------------- Stage 1: deterministic global sum of |a| + 1e-12 (fp64) ----
__global__ void k_sum_partial(const float* __restrict__ a) {
    __shared__ double wsum[8];
    const int b = blockIdx.x, t = threadIdx.x;
    const float4* p = (const float4*)(a + (size_t)b * 8192);
    double acc = 0.0;
    #pragma unroll
    for (int j = 0; j < 8; j++) {
        float4 v = p[t + j * 256];
        acc += (fabs((double)v.x) + 1e-12) + (fabs((double)v.y) + 1e-12)
             + (fabs((double)v.z) + 1e-12) + (fabs((double)v.w) + 1e-12);
    }
    #pragma unroll
    for (int o = 16; o > 0; o >>= 1) acc += __shfl_down_sync(0xffffffffu, acc, o);
    if ((t & 31) == 0) wsum[t >> 5] = acc;
    __syncthreads();
    if (t == 0) {
        double s = 0.0;
        #pragma unroll
        for (int w = 0; w < 8; w++) s += wsum[w];
        g_partial[b] = s;
    }
}

__global__ void k_sum_final() {
    __shared__ double wsum[8];
    const int t = threadIdx.x;
    double acc = 0.0;
    for (int j = t; j < 2048; j += 256) acc += g_partial[j];
    #pragma unroll
    for (int o = 16; o > 0; o >>= 1) acc += __shfl_down_sync(0xffffffffu, acc, o);
    if ((t & 31) == 0) wsum[t >> 5] = acc;
    __syncthreads();
    if (t == 0) {
        double s = 0.0;
        for (int w = 0; w < 8; w++) s += wsum[w];
        g_invSf = (float)(1.0 / s);
    }
}

// ---------------- Stage 2: fused 6-quantity box filter -> (A,b) ----------------
// Stage (ax,ay) fp32 + a fp16 (a feeds only fp16-bound / S-correction paths).
// h-planes: (h1,h4)=fp32, (h0,h3)/(h2,h5)=fp16. smem 37.6 KB -> 6 blocks/SM.
__global__ __launch_bounds__(NTHR, 6) void k_stats(
    const float* __restrict__ X, const float* __restrict__ Y,
    const float* __restrict__ Wt)
{
    extern __shared__ unsigned char smem_raw[];
    float2*  sP  = (float2*)smem_raw;                // [HR*PIN2] (ax, ay) fp32
    __half*  sAh = (__half*)(sP + HR * PIN2);        // [HR*PINH] a fp16
    float2*  sF  = (float2*)(sAh + HR * PINH);       // (h1=a2xy, h4=a2x2) fp32
    __half2* sG  = (__half2*)(sF + HR * PH2);        // (h0=a,    h3=ay)   fp16
    __half2* sK  = sG + HR * PH2;                    // (h2=a2x,  h5=ax)   fp16

    const int tid = threadIdx.x;
    const int img = blockIdx.z;
    const int bc  = blockIdx.x * TC;
    const int br  = blockIdx.y * TR;
    const size_t ibase = (size_t)img * (HH * WW);

    // ---- Phase A: vectorized halo load (zero outside = truncated box) ----
    #pragma unroll
    for (int it = 0; it < 2; ++it) {
        const int idx = tid + it * NTHR;
        if (idx < HR * (HC / 4)) {                 // 400 items
            const int rh = idx / (HC / 4);
            const int vq = idx % (HC / 4);
            const int gr = br - RR + rh;
            const int gc = bc - RR + vq * 4;       // multiple of 4, aligned
            float4 xv = make_float4(0.f,0.f,0.f,0.f);
            float4 yv = xv, av = xv;
            if (gr >= 0 && gr < HH && gc >= 0 && gc < WW) {
                const size_t o = ibase + (size_t)gr * WW + gc;
                xv = *(const float4*)(X  + o);
                yv = *(const float4*)(Y  + o);
                av = *(const float4*)(Wt + o);
            }
            const float a0 = fabsf(av.x)+1e-12f, a1 = fabsf(av.y)+1e-12f;
            const float a2 = fabsf(av.z)+1e-12f, a3 = fabsf(av.w)+1e-12f;
            const int sb2 = rh * PIN2 + vq * 4;
            sP[sb2+0] = make_float2(a0*xv.x, a0*yv.x);
            sP[sb2+1] = make_float2(a1*xv.y, a1*yv.y);
            sP[sb2+2] = make_float2(a2*xv.z, a2*yv.z);
            sP[sb2+3] = make_float2(a3*xv.w, a3*yv.w);
            const int sbh = rh * PINH + vq * 4;
            sAh[sbh+0] = __float2half_rn(a0);
            sAh[sbh+1] = __float2half_rn(a1);
            sAh[sbh+2] = __float2half_rn(a2);
            sAh[sbh+3] = __float2half_rn(a3);
        }
    }
    __syncthreads();

    // ---- Phase B: horizontal 9-tap, sliding over 4 cols per thread ----
    // step 1: rows 0..31 (all 256 threads); step 2: rows 32..39 (64 threads)
    #pragma unroll
    for (int step = 0; step < 2; ++step) {
        int rh, cg;
        bool act;
        if (step == 0) { rh = tid & 31;          cg = tid >> 5; act = true; }
        else           { rh = 32 + (tid & 7);    cg = tid >> 3; act = (tid < 64); }
        if (act) {
            const int b2 = rh * PIN2 + cg * 4;
            const int bH = rh * PINH + cg * 4;
            const int hb = rh * PH2  + cg * 4;

            float h0=0.f,h1=0.f,h2=0.f,h3=0.f,h4=0.f,h5=0.f;
            #pragma unroll
            for (int d = 0; d < 9; ++d) {
                const float2 p = sP[b2 + d];              // (ax, ay)
                const float  a = __half2float(sAh[bH + d]);
                h0 += a; h5 += p.x; h3 += p.y;
                h2 = fmaf(a,   p.x, h2);                  // a2x
                h1 = fmaf(p.x, p.y, h1);                  // a2xy
                h4 = fmaf(p.x, p.x, h4);                  // a2x2
            }
            sF[hb] = make_float2(h1, h4);
            sG[hb] = __floats2half2_rn(h0, h3);
            sK[hb] = __floats2half2_rn(h2, h5);

            #pragma unroll
            for (int s = 1; s < 4; ++s) {
                float2 p = sP[b2 + 8 + s];
                float  a = __half2float(sAh[bH + 8 + s]);
                h0 += a; h5 += p.x; h3 += p.y;
                h2 = fmaf(a,   p.x, h2);
                h1 = fmaf(p.x, p.y, h1);
                h4 = fmaf(p.x, p.x, h4);
                p = sP[b2 + s - 1];
                a = __half2float(sAh[bH + s - 1]);
                h0 -= a; h5 -= p.x; h3 -= p.y;
                h2 = fmaf(-a,   p.x, h2);
                h1 = fmaf(-p.x, p.y, h1);
                h4 = fmaf(-p.x, p.x, h4);
                sF[hb+s] = make_float2(h1, h4);
                sG[hb+s] = __floats2half2_rn(h0, h3);
                sK[hb+s] = __floats2half2_rn(h2, h5);
            }
        }
    }
    __syncthreads();

    // ---- Phase C: vertical 9-tap, 4-row runs, all 256 threads + solve ----
    {
        const int c   = tid & 31;
        const int seg = tid >> 5;            // 0..7 -> rows seg*4 ..
        const int col = bc + c;
        const int ncl = min(col + RR, WW - 1) - max(col - RR, 0) + 1;
        const float invS = g_invSf;
        const int r0 = seg * 4;

        float a0=0.f,a1=0.f,a2=0.f,a3=0.f,a4=0.f,a5=0.f;
        #pragma unroll
        for (int d = 0; d < 9; ++d) {
            const int hb = (r0 + d) * PH2 + c;
            const float2 f = sF[hb];
            const float2 g = __half22float2(sG[hb]);
            const float2 k = __half22float2(sK[hb]);
            a1 += f.x; a4 += f.y;
            a0 += g.x; a3 += g.y;
            a2 += k.x; a5 += k.y;
        }
        #pragma unroll
        for (int i = 0; i < 4; ++i) {
            const int gro = br + r0 + i;     // always < HH (512 = 16*32)
            {
                const int nr = min(gro + RR, HH - 1) - max(gro - RR, 0) + 1;
                const float Nf  = (float)(nr * ncl);
                const float num = fmaf(-(a2 * a3), invS, a1);
                const float den = fabsf(fmaf(-(a2 * a5), invS, a4)) + Nf * 1e-8f;
                const float Av  = __fdividef(num, den);
                const float bv  = __fdividef(fmaf(-Av, a5, a3), a0);
                g_ABh[ibase + (size_t)gro * WW + col] = __floats2half2_rn(Av, bv);
            }
            if (i < 3) {
                const int ha = (r0 + 9 + i) * PH2 + c;
                const int hs = (r0 + i) * PH2 + c;
                const float2 fa = sF[ha], fs = sF[hs];
                const float2 ga = __half22float2(sG[ha]), gs = __half22float2(sG[hs]);
                const float2 ka = __half22float2(sK[ha]), ks = __half22float2(sK[hs]);
                a1 += fa.x - fs.x; a4 += fa.y - fs.y;
                a0 += ga.x - gs.x; a3 += ga.y - gs.y;
                a2 += ka.x - ks.x; a5 += ka.y - ks.y;
            }
        }
    }
}

// ---------------- Stage 3: box filter (A,b) fp16 + final blend -----------------
__global__ __launch_bounds__(NTHR) void k_final(
    const float* __restrict__ X, float* __restrict__ out)
{
    __shared__ __half2 sABh[HR * PAB];      // (A, b) fp16
    __shared__ float2  sHab[HR * PH2];      // h sums fp32

    const int tid = threadIdx.x;
    const int img = blockIdx.z;
    const int bc  = blockIdx.x * TC;
    const int br  = blockIdx.y * TR;
    const size_t ibase = (size_t)img * (HH * WW);

    // Phase A: uint4 = 4 pixels of half2 (A,b); 400 items
    #pragma unroll
    for (int it = 0; it < 2; ++it) {
        const int idx = tid + it * NTHR;
        if (idx < HR * (HC / 4)) {
            const int rh = idx / (HC / 4);
            const int vq = idx % (HC / 4);
            const int gr = br - RR + rh;
            const int gc = bc - RR + vq * 4;      // multiple of 4 -> 16B aligned
            uint4 v = make_uint4(0u, 0u, 0u, 0u);
            if (gr >= 0 && gr < HH && gc >= 0 && gc < WW) {
                const size_t o = ibase + (size_t)gr * WW + gc;
                v = *(const uint4*)(g_ABh + o);
            }
            const int sb = rh * PAB + vq * 4;
            sABh[sb+0] = *reinterpret_cast<__half2*>(&v.x);
            sABh[sb+1] = *reinterpret_cast<__half2*>(&v.y);
            sABh[sb+2] = *reinterpret_cast<__half2*>(&v.z);
            sABh[sb+3] = *reinterpret_cast<__half2*>(&v.w);
        }
    }
    __syncthreads();

    // Phase B: horizontal 9-tap, 4-col runs (rows 0..31 by 256 thr, 32..39 by 64)
    #pragma unroll
    for (int step = 0; step < 2; ++step) {
        int rh, cg;
        bool act;
        if (step == 0) { rh = tid & 31;          cg = tid >> 5; act = true; }
        else           { rh = 32 + (tid & 7);    cg = tid >> 3; act = (tid < 64); }
        if (act) {
            const int b2 = rh * PAB + cg * 4;
            const int hb = rh * PH2 + cg * 4;
            float hA = 0.f, hB = 0.f;
            #pragma unroll
            for (int d = 0; d < 9; ++d) {
                const float2 ab = __half22float2(sABh[b2 + d]);
                hA += ab.x; hB += ab.y;
            }
            sHab[hb] = make_float2(hA, hB);
            #pragma unroll
            for (int s = 1; s < 4; ++s) {
                const float2 aa = __half22float2(sABh[b2 + 8 + s]);
                const float2 as = __half22float2(sABh[b2 + s - 1]);
                hA += aa.x - as.x;
                hB += aa.y - as.y;
                sHab[hb + s] = make_float2(hA, hB);
            }
        }
    }
    __syncthreads();

    // Phase C: vertical 9-tap, 4-row runs, all 256 threads + blend
    {
        const int c   = tid & 31;
        const int seg = tid >> 5;
        const int col = bc + c;
        const int ncl = min(col + RR, WW - 1) - max(col - RR, 0) + 1;
        const int r0 = seg * 4;

        float xv[4];
        #pragma unroll
        for (int i = 0; i < 4; ++i)
            xv[i] = X[ibase + (size_t)(br + r0 + i) * WW + col];

        float aA = 0.f, aB = 0.f;
        #pragma unroll
        for (int d = 0; d < 9; ++d) {
            const float2 h = sHab[(r0 + d) * PH2 + c];
            aA += h.x; aB += h.y;
        }
        #pragma unroll
        for (int i = 0; i < 4; ++i) {
            const int gro = br + r0 + i;     // always < HH
            const int nr = min(gro + RR, HH - 1) - max(gro - RR, 0) + 1;
            const float rcpN = __fdividef(1.f, (float)(nr * ncl));
            out[ibase + (size_t)gro * WW + col] = (aA * xv[i] + aB) * rcpN;
            if (i < 3) {
                const float2 ha = sHab[(r0 + 9 + i) * PH2 + c];
                const float2 hs = sHab[(r0 + i) * PH2 + c];
                aA += ha.x - hs.x;
                aB += ha.y - hs.y;
            }
        }
    }
}

extern "C" void kernel_launch(void* const* d_in, const int* in_sizes, int n_in,
                              void* d_out, int out_size) {
    const float* x = (const float*)d_in[0];  // lr_x
    const float* y = (const float*)d_in[1];  // lr_y
    const float* a = (const float*)d_in[2];  // l_a
    float* out = (float*)d_out;

    k_sum_partial<<<2048, 256>>>(a);
    k_sum_final<<<1, 256>>>();

    // smem: P 13120 + a(half) 3360 + F 10560 + G 5280 + K 5280 = 37600 B -> 6 blocks/SM
    const int smem_stats = HR * PIN2 * 8 + HR * PINH * 2
                         + HR * PH2 * 8 + 2 * (HR * PH2 * 4);
    cudaFuncSetAttribute(k_stats, cudaFuncAttributeMaxDynamicSharedMemorySize, smem_stats);

    dim3 grid(WW / TC, GY, NIMG);  // 16 x 16 x 64
    k_stats<<<grid, NTHR, smem_stats>>>(x, y, a);
    k_final<<<grid, NTHR>>>(x, out);
}

// round 12
// speedup vs baseline: 1.9137x; 1.5959x over previous
#include <cuda_runtime.h>
#include <cuda_fp16.h>
#include <math.h>

#define HH 512
#define WW 512
#define RR 4
#define NIMG 64
#define NEL (NIMG*HH*WW)

// tile geometry: TR=32 -> no row-bound checks (512/32=16)
#define TC 32             // output cols per block
#define TR 32             // output rows per block
#define HR 40             // halo rows
#define HC 40             // halo cols
#define PIN2 41           // float2 plane pitch (float2s) -> conflict-free
#define PINH 42           // half plane pitch (halves)    -> conflict-free
#define PH2 33            // h plane pitch (elements)     -> conflict-free
#define PAB 41            // k_final A,b half2 pitch      -> conflict-free
#define NTHR 256
#define GY (HH / TR)      // 16

// Scratch (device global: no allocation allowed)
__device__ __half2 g_ABh[NEL];    // interleaved (A, b) in fp16

// ---------------- Stage 1: fused 5-quantity box filter -> (A,b) ----------------
// S-correction terms (|.|*1e-7 relative) dropped => no global sum needed and
// the a^2x quantity disappears. Quantities: a, ax, ay, a2xy=ax*ay, a2x2=ax^2.
// h-planes: F=(a2xy,a2x2) fp32, G=(a,ay) fp16, K=ax fp16. smem 35.0 KB.
__global__ __launch_bounds__(NTHR, 6) void k_stats(
    const float* __restrict__ X, const float* __restrict__ Y,
    const float* __restrict__ Wt)
{
    extern __shared__ unsigned char smem_raw[];
    float2*  sP  = (float2*)smem_raw;                // [HR*PIN2] (ax, ay) fp32
    __half*  sAh = (__half*)(sP + HR * PIN2);        // [HR*PINH] a fp16
    float2*  sF  = (float2*)(sAh + HR * PINH);       // (h1=a2xy, h4=a2x2) fp32
    __half2* sG  = (__half2*)(sF + HR * PH2);        // (h0=a,    h3=ay)   fp16
    __half*  sK  = (__half*)(sG + HR * PH2);         // h5=ax              fp16

    const int tid = threadIdx.x;
    const int img = blockIdx.z;
    const int bc  = blockIdx.x * TC;
    const int br  = blockIdx.y * TR;
    const size_t ibase = (size_t)img * (HH * WW);

    // ---- Phase A: vectorized halo load (zero outside = truncated box) ----
    #pragma unroll
    for (int it = 0; it < 2; ++it) {
        const int idx = tid + it * NTHR;
        if (idx < HR * (HC / 4)) {                 // 400 items
            const int rh = idx / (HC / 4);
            const int vq = idx % (HC / 4);
            const int gr = br - RR + rh;
            const int gc = bc - RR + vq * 4;       // multiple of 4, aligned
            float4 xv = make_float4(0.f,0.f,0.f,0.f);
            float4 yv = xv, av = xv;
            if (gr >= 0 && gr < HH && gc >= 0 && gc < WW) {
                const size_t o = ibase + (size_t)gr * WW + gc;
                xv = *(const float4*)(X  + o);
                yv = *(const float4*)(Y  + o);
                av = *(const float4*)(Wt + o);
            }
            const float a0 = fabsf(av.x)+1e-12f, a1 = fabsf(av.y)+1e-12f;
            const float a2 = fabsf(av.z)+1e-12f, a3 = fabsf(av.w)+1e-12f;
            const int sb2 = rh * PIN2 + vq * 4;
            sP[sb2+0] = make_float2(a0*xv.x, a0*yv.x);
            sP[sb2+1] = make_float2(a1*xv.y, a1*yv.y);
            sP[sb2+2] = make_float2(a2*xv.z, a2*yv.z);
            sP[sb2+3] = make_float2(a3*xv.w, a3*yv.w);
            const int sbh = rh * PINH + vq * 4;
            sAh[sbh+0] = __float2half_rn(a0);
            sAh[sbh+1] = __float2half_rn(a1);
            sAh[sbh+2] = __float2half_rn(a2);
            sAh[sbh+3] = __float2half_rn(a3);
        }
    }
    __syncthreads();

    // ---- Phase B: horizontal 9-tap, sliding over 4 cols per thread ----
    // step 1: rows 0..31 (all 256 threads); step 2: rows 32..39 (64 threads)
    #pragma unroll
    for (int step = 0; step < 2; ++step) {
        int rh, cg;
        bool act;
        if (step == 0) { rh = tid & 31;          cg = tid >> 5; act = true; }
        else           { rh = 32 + (tid & 7);    cg = tid >> 3; act = (tid < 64); }
        if (act) {
            const int b2 = rh * PIN2 + cg * 4;
            const int bH = rh * PINH + cg * 4;
            const int hb = rh * PH2  + cg * 4;

            float h0=0.f,h1=0.f,h3=0.f,h4=0.f,h5=0.f;
            #pragma unroll
            for (int d = 0; d < 9; ++d) {
                const float2 p = sP[b2 + d];              // (ax, ay)
                const float  a = __half2float(sAh[bH + d]);
                h0 += a; h5 += p.x; h3 += p.y;
                h1 = fmaf(p.x, p.y, h1);                  // a2xy
                h4 = fmaf(p.x, p.x, h4);                  // a2x2
            }
            sF[hb] = make_float2(h1, h4);
            sG[hb] = __floats2half2_rn(h0, h3);
            sK[hb] = __float2half_rn(h5);

            #pragma unroll
            for (int s = 1; s < 4; ++s) {
                float2 p = sP[b2 + 8 + s];
                float  a = __half2float(sAh[bH + 8 + s]);
                h0 += a; h5 += p.x; h3 += p.y;
                h1 = fmaf(p.x, p.y, h1);
                h4 = fmaf(p.x, p.x, h4);
                p = sP[b2 + s - 1];
                a = __half2float(sAh[bH + s - 1]);
                h0 -= a; h5 -= p.x; h3 -= p.y;
                h1 = fmaf(-p.x, p.y, h1);
                h4 = fmaf(-p.x, p.x, h4);
                sF[hb+s] = make_float2(h1, h4);
                sG[hb+s] = __floats2half2_rn(h0, h3);
                sK[hb+s] = __float2half_rn(h5);
            }
        }
    }
    __syncthreads();

    // ---- Phase C: vertical 9-tap, 4-row runs, all 256 threads + solve ----
    {
        const int c   = tid & 31;
        const int seg = tid >> 5;            // 0..7 -> rows seg*4 ..
        const int col = bc + c;
        const int ncl = min(col + RR, WW - 1) - max(col - RR, 0) + 1;
        const int r0 = seg * 4;

        float a0=0.f,a1=0.f,a3=0.f,a4=0.f,a5=0.f;
        #pragma unroll
        for (int d = 0; d < 9; ++d) {
            const int hb = (r0 + d) * PH2 + c;
            const float2 f = sF[hb];
            const float2 g = __half22float2(sG[hb]);
            a1 += f.x; a4 += f.y;
            a0 += g.x; a3 += g.y;
            a5 += __half2float(sK[hb]);
        }
        #pragma unroll
        for (int i = 0; i < 4; ++i) {
            const int gro = br + r0 + i;     // always < HH (512 = 16*32)
            {
                const int nr = min(gro + RR, HH - 1) - max(gro - RR, 0) + 1;
                const float Nf  = (float)(nr * ncl);
                const float den = fabsf(a4) + Nf * 1e-8f;
                const float Av  = __fdividef(a1, den);
                const float bv  = __fdividef(fmaf(-Av, a5, a3), a0);
                g_ABh[ibase + (size_t)gro * WW + col] = __floats2half2_rn(Av, bv);
            }
            if (i < 3) {
                const int ha = (r0 + 9 + i) * PH2 + c;
                const int hs = (r0 + i) * PH2 + c;
                const float2 fa = sF[ha], fs = sF[hs];
                const float2 ga = __half22float2(sG[ha]), gs = __half22float2(sG[hs]);
                a1 += fa.x - fs.x; a4 += fa.y - fs.y;
                a0 += ga.x - gs.x; a3 += ga.y - gs.y;
                a5 += __half2float(sK[ha]) - __half2float(sK[hs]);
            }
        }
    }
}

// ---------------- Stage 2: box filter (A,b) fp16 + final blend -----------------
__global__ __launch_bounds__(NTHR) void k_final(
    const float* __restrict__ X, float* __restrict__ out)
{
    __shared__ __half2 sABh[HR * PAB];      // (A, b) fp16
    __shared__ float2  sHab[HR * PH2];      // h sums fp32

    const int tid = threadIdx.x;
    const int img = blockIdx.z;
    const int bc  = blockIdx.x * TC;
    const int br  = blockIdx.y * TR;
    const size_t ibase = (size_t)img * (HH * WW);

    // Phase A: uint4 = 4 pixels of half2 (A,b); 400 items
    #pragma unroll
    for (int it = 0; it < 2; ++it) {
        const int idx = tid + it * NTHR;
        if (idx < HR * (HC / 4)) {
            const int rh = idx / (HC / 4);
            const int vq = idx % (HC / 4);
            const int gr = br - RR + rh;
            const int gc = bc - RR + vq * 4;      // multiple of 4 -> 16B aligned
            uint4 v = make_uint4(0u, 0u, 0u, 0u);
            if (gr >= 0 && gr < HH && gc >= 0 && gc < WW) {
                const size_t o = ibase + (size_t)gr * WW + gc;
                v = *(const uint4*)(g_ABh + o);
            }
            const int sb = rh * PAB + vq * 4;
            sABh[sb+0] = *reinterpret_cast<__half2*>(&v.x);
            sABh[sb+1] = *reinterpret_cast<__half2*>(&v.y);
            sABh[sb+2] = *reinterpret_cast<__half2*>(&v.z);
            sABh[sb+3] = *reinterpret_cast<__half2*>(&v.w);
        }
    }
    __syncthreads();

    // Phase B: horizontal 9-tap, 4-col runs (rows 0..31 by 256 thr, 32..39 by 64)
    #pragma unroll
    for (int step = 0; step < 2; ++step) {
        int rh, cg;
        bool act;
        if (step == 0) { rh = tid & 31;          cg = tid >> 5; act = true; }
        else           { rh = 32 + (tid & 7);    cg = tid >> 3; act = (tid < 64); }
        if (act) {
            const int b2 = rh * PAB + cg * 4;
            const int hb = rh * PH2 + cg * 4;
            float hA = 0.f, hB = 0.f;
            #pragma unroll
            for (int d = 0; d < 9; ++d) {
                const float2 ab = __half22float2(sABh[b2 + d]);
                hA += ab.x; hB += ab.y;
            }
            sHab[hb] = make_float2(hA, hB);
            #pragma unroll
            for (int s = 1; s < 4; ++s) {
                const float2 aa = __half22float2(sABh[b2 + 8 + s]);
                const float2 as = __half22float2(sABh[b2 + s - 1]);
                hA += aa.x - as.x;
                hB += aa.y - as.y;
                sHab[hb + s] = make_float2(hA, hB);
            }
        }
    }
    __syncthreads();

    // Phase C: vertical 9-tap, 4-row runs, all 256 threads + blend
    {
        const int c   = tid & 31;
        const int seg = tid >> 5;
        const int col = bc + c;
        const int ncl = min(col + RR, WW - 1) - max(col - RR, 0) + 1;
        const int r0 = seg * 4;

        float xv[4];
        #pragma unroll
        for (int i = 0; i < 4; ++i)
            xv[i] = X[ibase + (size_t)(br + r0 + i) * WW + col];

        float aA = 0.f, aB = 0.f;
        #pragma unroll
        for (int d = 0; d < 9; ++d) {
            const float2 h = sHab[(r0 + d) * PH2 + c];
            aA += h.x; aB += h.y;
        }
        #pragma unroll
        for (int i = 0; i < 4; ++i) {
            const int gro = br + r0 + i;     // always < HH
            const int nr = min(gro + RR, HH - 1) - max(gro - RR, 0) + 1;
            const float rcpN = __fdividef(1.f, (float)(nr * ncl));
            out[ibase + (size_t)gro * WW + col] = (aA * xv[i] + aB) * rcpN;
            if (i < 3) {
                const float2 ha = sHab[(r0 + 9 + i) * PH2 + c];
                const float2 hs = sHab[(r0 + i) * PH2 + c];
                aA += ha.x - hs.x;
                aB += ha.y - hs.y;
            }
        }
    }
}

extern "C" void kernel_launch(void* const* d_in, const int* in_sizes, int n_in,
                              void* d_out, int out_size) {
    const float* x = (const float*)d_in[0];  // lr_x
    const float* y = (const float*)d_in[1];  // lr_y
    const float* a = (const float*)d_in[2];  // l_a
    float* out = (float*)d_out;

    // smem: P 13120 + a(half) 3360 + F 10560 + G 5280 + K 2640 = 34960 B -> 6 blocks/SM
    const int smem_stats = HR * PIN2 * 8 + HR * PINH * 2
                         + HR * PH2 * 8 + HR * PH2 * 4 + HR * PH2 * 2;
    cudaFuncSetAttribute(k_stats, cudaFuncAttributeMaxDynamicSharedMemorySize, smem_stats);

    dim3 grid(WW / TC, GY, NIMG);  // 16 x 16 x 64
    k_stats<<<grid, NTHR, smem_stats>>>(x, y, a);
    k_final<<<grid, NTHR>>>(x, out);
}

// round 13
// speedup vs baseline: 2.0610x; 1.0770x over previous
#include <cuda_runtime.h>
#include <cuda_fp16.h>
#include <math.h>

#define HH 512
#define WW 512
#define RR 4
#define NIMG 64
#define NEL (NIMG*HH*WW)

// tile geometry: TR=32 -> no row-bound checks (512/32=16)
#define TC 32             // output cols per block
#define TR 32             // output rows per block
#define HR 40             // halo rows
#define HC 40             // halo cols
#define PP2 41            // half2 (ax,ay) plane pitch (half2s) -> conflict-free
#define PINH 42           // half plane pitch (halves)          -> conflict-free
#define PH2 33            // h plane pitch (elements)           -> conflict-free
#define PAB 41            // k_final A,b half2 pitch            -> conflict-free
#define NTHR 256
#define GY (HH / TR)      // 16

// Scratch (device global: no allocation allowed)
__device__ __half2 g_ABh[NEL];    // interleaved (A, b) in fp16

// ---------------- Stage 1: fused 5-quantity box filter -> (A,b) ----------------
// Quantities: a, ax, ay, a2xy=ax*ay, a2x2=ax^2 (S-corrections dropped, ~1e-7 rel).
// All staging fp16: P=(ax,ay) half2, a half. h-planes: F=(a2xy,a2x2) fp32,
// G=(a,ay) fp16, K=ax fp16. smem 28.4 KB -> 7 blocks/SM (56 warps).
__global__ __launch_bounds__(NTHR, 7) void k_stats(
    const float* __restrict__ X, const float* __restrict__ Y,
    const float* __restrict__ Wt)
{
    extern __shared__ unsigned char smem_raw[];
    __half2* sP  = (__half2*)smem_raw;               // [HR*PP2] (ax, ay) fp16
    __half*  sAh = (__half*)(sP + HR * PP2);         // [HR*PINH] a fp16
    float2*  sF  = (float2*)(sAh + HR * PINH);       // (h1=a2xy, h4=a2x2) fp32
    __half2* sG  = (__half2*)(sF + HR * PH2);        // (h0=a,    h3=ay)   fp16
    __half*  sK  = (__half*)(sG + HR * PH2);         // h5=ax              fp16

    const int tid = threadIdx.x;
    const int img = blockIdx.z;
    const int bc  = blockIdx.x * TC;
    const int br  = blockIdx.y * TR;
    const size_t ibase = (size_t)img * (HH * WW);

    // ---- Phase A: vectorized halo load (zero outside = truncated box) ----
    #pragma unroll
    for (int it = 0; it < 2; ++it) {
        const int idx = tid + it * NTHR;
        if (idx < HR * (HC / 4)) {                 // 400 items
            const int rh = idx / (HC / 4);
            const int vq = idx % (HC / 4);
            const int gr = br - RR + rh;
            const int gc = bc - RR + vq * 4;       // multiple of 4, aligned
            float4 xv = make_float4(0.f,0.f,0.f,0.f);
            float4 yv = xv, av = xv;
            if (gr >= 0 && gr < HH && gc >= 0 && gc < WW) {
                const size_t o = ibase + (size_t)gr * WW + gc;
                xv = *(const float4*)(X  + o);
                yv = *(const float4*)(Y  + o);
                av = *(const float4*)(Wt + o);
            }
            const float a0 = fabsf(av.x)+1e-12f, a1 = fabsf(av.y)+1e-12f;
            const float a2 = fabsf(av.z)+1e-12f, a3 = fabsf(av.w)+1e-12f;
            const int sb2 = rh * PP2 + vq * 4;
            sP[sb2+0] = __floats2half2_rn(a0*xv.x, a0*yv.x);
            sP[sb2+1] = __floats2half2_rn(a1*xv.y, a1*yv.y);
            sP[sb2+2] = __floats2half2_rn(a2*xv.z, a2*yv.z);
            sP[sb2+3] = __floats2half2_rn(a3*xv.w, a3*yv.w);
            const int sbh = rh * PINH + vq * 4;
            sAh[sbh+0] = __float2half_rn(a0);
            sAh[sbh+1] = __float2half_rn(a1);
            sAh[sbh+2] = __float2half_rn(a2);
            sAh[sbh+3] = __float2half_rn(a3);
        }
    }
    __syncthreads();

    // ---- Phase B: horizontal 9-tap, sliding over 4 cols per thread ----
    // step 1: rows 0..31 (all 256 threads); step 2: rows 32..39 (64 threads)
    #pragma unroll
    for (int step = 0; step < 2; ++step) {
        int rh, cg;
        bool act;
        if (step == 0) { rh = tid & 31;          cg = tid >> 5; act = true; }
        else           { rh = 32 + (tid & 7);    cg = tid >> 3; act = (tid < 64); }
        if (act) {
            const int b2 = rh * PP2  + cg * 4;
            const int bH = rh * PINH + cg * 4;
            const int hb = rh * PH2  + cg * 4;

            float h0=0.f,h1=0.f,h3=0.f,h4=0.f,h5=0.f;
            #pragma unroll
            for (int d = 0; d < 9; ++d) {
                const float2 p = __half22float2(sP[b2 + d]);   // (ax, ay)
                const float  a = __half2float(sAh[bH + d]);
                h0 += a; h5 += p.x; h3 += p.y;
                h1 = fmaf(p.x, p.y, h1);                       // a2xy
                h4 = fmaf(p.x, p.x, h4);                       // a2x2
            }
            sF[hb] = make_float2(h1, h4);
            sG[hb] = __floats2half2_rn(h0, h3);
            sK[hb] = __float2half_rn(h5);

            #pragma unroll
            for (int s = 1; s < 4; ++s) {
                float2 p = __half22float2(sP[b2 + 8 + s]);
                float  a = __half2float(sAh[bH + 8 + s]);
                h0 += a; h5 += p.x; h3 += p.y;
                h1 = fmaf(p.x, p.y, h1);
                h4 = fmaf(p.x, p.x, h4);
                p = __half22float2(sP[b2 + s - 1]);
                a = __half2float(sAh[bH + s - 1]);
                h0 -= a; h5 -= p.x; h3 -= p.y;
                h1 = fmaf(-p.x, p.y, h1);
                h4 = fmaf(-p.x, p.x, h4);
                sF[hb+s] = make_float2(h1, h4);
                sG[hb+s] = __floats2half2_rn(h0, h3);
                sK[hb+s] = __float2half_rn(h5);
            }
        }
    }
    __syncthreads();

    // ---- Phase C: vertical 9-tap, 4-row runs, all 256 threads + solve ----
    {
        const int c   = tid & 31;
        const int seg = tid >> 5;            // 0..7 -> rows seg*4 ..
        const int col = bc + c;
        const int ncl = min(col + RR, WW - 1) - max(col - RR, 0) + 1;
        const int r0 = seg * 4;

        float a0=0.f,a1=0.f,a3=0.f,a4=0.f,a5=0.f;
        #pragma unroll
        for (int d = 0; d < 9; ++d) {
            const int hb = (r0 + d) * PH2 + c;
            const float2 f = sF[hb];
            const float2 g = __half22float2(sG[hb]);
            a1 += f.x; a4 += f.y;
            a0 += g.x; a3 += g.y;
            a5 += __half2float(sK[hb]);
        }
        #pragma unroll
        for (int i = 0; i < 4; ++i) {
            const int gro = br + r0 + i;     // always < HH (512 = 16*32)
            {
                const int nr = min(gro + RR, HH - 1) - max(gro - RR, 0) + 1;
                const float Nf  = (float)(nr * ncl);
                const float den = fabsf(a4) + Nf * 1e-8f;
                const float Av  = __fdividef(a1, den);
                const float bv  = __fdividef(fmaf(-Av, a5, a3), a0);
                g_ABh[ibase + (size_t)gro * WW + col] = __floats2half2_rn(Av, bv);
            }
            if (i < 3) {
                const int ha = (r0 + 9 + i) * PH2 + c;
                const int hs = (r0 + i) * PH2 + c;
                const float2 fa = sF[ha], fs = sF[hs];
                const float2 ga = __half22float2(sG[ha]), gs = __half22float2(sG[hs]);
                a1 += fa.x - fs.x; a4 += fa.y - fs.y;
                a0 += ga.x - gs.x; a3 += ga.y - gs.y;
                a5 += __half2float(sK[ha]) - __half2float(sK[hs]);
            }
        }
    }
}

// ---------------- Stage 2: box filter (A,b) fp16 + final blend -----------------
__global__ __launch_bounds__(NTHR) void k_final(
    const float* __restrict__ X, float* __restrict__ out)
{
    __shared__ __half2 sABh[HR * PAB];      // (A, b) fp16
    __shared__ float2  sHab[HR * PH2];      // h sums fp32

    const int tid = threadIdx.x;
    const int img = blockIdx.z;
    const int bc  = blockIdx.x * TC;
    const int br  = blockIdx.y * TR;
    const size_t ibase = (size_t)img * (HH * WW);

    // Phase A: uint4 = 4 pixels of half2 (A,b); 400 items
    #pragma unroll
    for (int it = 0; it < 2; ++it) {
        const int idx = tid + it * NTHR;
        if (idx < HR * (HC / 4)) {
            const int rh = idx / (HC / 4);
            const int vq = idx % (HC / 4);
            const int gr = br - RR + rh;
            const int gc = bc - RR + vq * 4;      // multiple of 4 -> 16B aligned
            uint4 v = make_uint4(0u, 0u, 0u, 0u);
            if (gr >= 0 && gr < HH && gc >= 0 && gc < WW) {
                const size_t o = ibase + (size_t)gr * WW + gc;
                v = *(const uint4*)(g_ABh + o);
            }
            const int sb = rh * PAB + vq * 4;
            sABh[sb+0] = *reinterpret_cast<__half2*>(&v.x);
            sABh[sb+1] = *reinterpret_cast<__half2*>(&v.y);
            sABh[sb+2] = *reinterpret_cast<__half2*>(&v.z);
            sABh[sb+3] = *reinterpret_cast<__half2*>(&v.w);
        }
    }
    __syncthreads();

    // Phase B: horizontal 9-tap, 4-col runs (rows 0..31 by 256 thr, 32..39 by 64)
    #pragma unroll
    for (int step = 0; step < 2; ++step) {
        int rh, cg;
        bool act;
        if (step == 0) { rh = tid & 31;          cg = tid >> 5; act = true; }
        else           { rh = 32 + (tid & 7);    cg = tid >> 3; act = (tid < 64); }
        if (act) {
            const int b2 = rh * PAB + cg * 4;
            const int hb = rh * PH2 + cg * 4;
            float hA = 0.f, hB = 0.f;
            #pragma unroll
            for (int d = 0; d < 9; ++d) {
                const float2 ab = __half22float2(sABh[b2 + d]);
                hA += ab.x; hB += ab.y;
            }
            sHab[hb] = make_float2(hA, hB);
            #pragma unroll
            for (int s = 1; s < 4; ++s) {
                const float2 aa = __half22float2(sABh[b2 + 8 + s]);
                const float2 as = __half22float2(sABh[b2 + s - 1]);
                hA += aa.x - as.x;
                hB += aa.y - as.y;
                sHab[hb + s] = make_float2(hA, hB);
            }
        }
    }
    __syncthreads();

    // Phase C: vertical 9-tap, 4-row runs, all 256 threads + blend
    {
        const int c   = tid & 31;
        const int seg = tid >> 5;
        const int col = bc + c;
        const int ncl = min(col + RR, WW - 1) - max(col - RR, 0) + 1;
        const int r0 = seg * 4;

        float xv[4];
        #pragma unroll
        for (int i = 0; i < 4; ++i)
            xv[i] = X[ibase + (size_t)(br + r0 + i) * WW + col];

        float aA = 0.f, aB = 0.f;
        #pragma unroll
        for (int d = 0; d < 9; ++d) {
            const float2 h = sHab[(r0 + d) * PH2 + c];
            aA += h.x; aB += h.y;
        }
        #pragma unroll
        for (int i = 0; i < 4; ++i) {
            const int gro = br + r0 + i;     // always < HH
            const int nr = min(gro + RR, HH - 1) - max(gro - RR, 0) + 1;
            const float rcpN = __fdividef(1.f, (float)(nr * ncl));
            out[ibase + (size_t)gro * WW + col] = (aA * xv[i] + aB) * rcpN;
            if (i < 3) {
                const float2 ha = sHab[(r0 + 9 + i) * PH2 + c];
                const float2 hs = sHab[(r0 + i) * PH2 + c];
                aA += ha.x - hs.x;
                aB += ha.y - hs.y;
            }
        }
    }
}

extern "C" void kernel_launch(void* const* d_in, const int* in_sizes, int n_in,
                              void* d_out, int out_size) {
    const float* x = (const float*)d_in[0];  // lr_x
    const float* y = (const float*)d_in[1];  // lr_y
    const float* a = (const float*)d_in[2];  // l_a
    float* out = (float*)d_out;

    // smem: P 6560 + a 3360 + F 10560 + G 5280 + K 2640 = 28400 B -> 7 blocks/SM
    const int smem_stats = HR * PP2 * 4 + HR * PINH * 2
                         + HR * PH2 * 8 + HR * PH2 * 4 + HR * PH2 * 2;
    cudaFuncSetAttribute(k_stats, cudaFuncAttributeMaxDynamicSharedMemorySize, smem_stats);

    dim3 grid(WW / TC, GY, NIMG);  // 16 x 16 x 64
    k_stats<<<grid, NTHR, smem_stats>>>(x, y, a);
    k_final<<<grid, NTHR>>>(x, out);
}

// round 14
// speedup vs baseline: 2.4418x; 1.1847x over previous
#include <cuda_runtime.h>
#include <cuda_fp16.h>
#include <math.h>

#define HH 512
#define WW 512
#define RR 4
#define NIMG 64
#define NEL (NIMG*HH*WW)

// tile geometry: TR=32 -> no row-bound checks (512/32=16)
#define TC 32             // output cols per block
#define TR 32             // output rows per block
#define HR 40             // halo rows
#define HC 40             // halo cols
#define PP2 41            // half2 (ax,ay) plane pitch (half2s) -> conflict-free
#define PINH 42           // half plane pitch (halves)          -> conflict-free
#define PH2 33            // h plane pitch (elements)           -> conflict-free
#define PAB 41            // k_final A,b half2 pitch            -> conflict-free
#define NTHR 256
#define GY (HH / TR)      // 16

// Scratch (device global: no allocation allowed)
__device__ __half2 g_ABh[NEL];    // interleaved (A, b) in fp16

__device__ __forceinline__ unsigned h2u(__half2 v) {
    return *reinterpret_cast<unsigned*>(&v);
}
__device__ __forceinline__ __half2 u2h(unsigned v) {
    return *reinterpret_cast<__half2*>(&v);
}

// ---------------- Stage 1: fused 5-quantity box filter -> (A,b) ----------------
// Quantities: a, ax, ay, a2xy=ax*ay, a2x2=ax^2 (S-corrections dropped).
// ALL staging/h-planes fp16. FG plane packs (h1,h4 | h0,h3) as one uint2
// (1 LDS.64 per tap), K holds h5=ax. smem 23.1 KB -> 8 blocks/SM (64 warps).
__global__ __launch_bounds__(NTHR, 8) void k_stats(
    const float* __restrict__ X, const float* __restrict__ Y,
    const float* __restrict__ Wt)
{
    extern __shared__ unsigned char smem_raw[];
    __half2* sP  = (__half2*)smem_raw;               // [HR*PP2] (ax, ay)
    __half*  sAh = (__half*)(sP + HR * PP2);         // [HR*PINH] a
    uint2*   sFG = (uint2*)(sAh + HR * PINH);        // [(h1,h4),(h0,h3)]
    __half*  sK  = (__half*)(sFG + HR * PH2);        // h5=ax

    const int tid = threadIdx.x;
    const int img = blockIdx.z;
    const int bc  = blockIdx.x * TC;
    const int br  = blockIdx.y * TR;
    const size_t ibase = (size_t)img * (HH * WW);

    // ---- Phase A: vectorized halo load (zero outside = truncated box) ----
    #pragma unroll
    for (int it = 0; it < 2; ++it) {
        const int idx = tid + it * NTHR;
        if (idx < HR * (HC / 4)) {                 // 400 items
            const int rh = idx / (HC / 4);
            const int vq = idx % (HC / 4);
            const int gr = br - RR + rh;
            const int gc = bc - RR + vq * 4;       // multiple of 4, aligned
            float4 xv = make_float4(0.f,0.f,0.f,0.f);
            float4 yv = xv, av = xv;
            if (gr >= 0 && gr < HH && gc >= 0 && gc < WW) {
                const size_t o = ibase + (size_t)gr * WW + gc;
                xv = *(const float4*)(X  + o);
                yv = *(const float4*)(Y  + o);
                av = *(const float4*)(Wt + o);
            }
            const float a0 = fabsf(av.x)+1e-12f, a1 = fabsf(av.y)+1e-12f;
            const float a2 = fabsf(av.z)+1e-12f, a3 = fabsf(av.w)+1e-12f;
            const int sb2 = rh * PP2 + vq * 4;
            sP[sb2+0] = __floats2half2_rn(a0*xv.x, a0*yv.x);
            sP[sb2+1] = __floats2half2_rn(a1*xv.y, a1*yv.y);
            sP[sb2+2] = __floats2half2_rn(a2*xv.z, a2*yv.z);
            sP[sb2+3] = __floats2half2_rn(a3*xv.w, a3*yv.w);
            const int sbh = rh * PINH + vq * 4;
            sAh[sbh+0] = __float2half_rn(a0);
            sAh[sbh+1] = __float2half_rn(a1);
            sAh[sbh+2] = __float2half_rn(a2);
            sAh[sbh+3] = __float2half_rn(a3);
        }
    }
    __syncthreads();

    // ---- Phase B: horizontal 9-tap, sliding over 4 cols per thread ----
    // step 1: rows 0..31 (all 256 threads); step 2: rows 32..39 (64 threads)
    #pragma unroll
    for (int step = 0; step < 2; ++step) {
        int rh, cg;
        bool act;
        if (step == 0) { rh = tid & 31;          cg = tid >> 5; act = true; }
        else           { rh = 32 + (tid & 7);    cg = tid >> 3; act = (tid < 64); }
        if (act) {
            const int b2 = rh * PP2  + cg * 4;
            const int bH = rh * PINH + cg * 4;
            const int hb = rh * PH2  + cg * 4;

            float h0=0.f,h1=0.f,h3=0.f,h4=0.f,h5=0.f;
            #pragma unroll
            for (int d = 0; d < 9; ++d) {
                const float2 p = __half22float2(sP[b2 + d]);   // (ax, ay)
                const float  a = __half2float(sAh[bH + d]);
                h0 += a; h5 += p.x; h3 += p.y;
                h1 = fmaf(p.x, p.y, h1);                       // a2xy
                h4 = fmaf(p.x, p.x, h4);                       // a2x2
            }
            sFG[hb] = make_uint2(h2u(__floats2half2_rn(h1, h4)),
                                 h2u(__floats2half2_rn(h0, h3)));
            sK[hb] = __float2half_rn(h5);

            #pragma unroll
            for (int s = 1; s < 4; ++s) {
                float2 p = __half22float2(sP[b2 + 8 + s]);
                float  a = __half2float(sAh[bH + 8 + s]);
                h0 += a; h5 += p.x; h3 += p.y;
                h1 = fmaf(p.x, p.y, h1);
                h4 = fmaf(p.x, p.x, h4);
                p = __half22float2(sP[b2 + s - 1]);
                a = __half2float(sAh[bH + s - 1]);
                h0 -= a; h5 -= p.x; h3 -= p.y;
                h1 = fmaf(-p.x, p.y, h1);
                h4 = fmaf(-p.x, p.x, h4);
                sFG[hb+s] = make_uint2(h2u(__floats2half2_rn(h1, h4)),
                                       h2u(__floats2half2_rn(h0, h3)));
                sK[hb+s] = __float2half_rn(h5);
            }
        }
    }
    __syncthreads();

    // ---- Phase C: vertical 9-tap, 4-row runs, all 256 threads + solve ----
    {
        const int c   = tid & 31;
        const int seg = tid >> 5;            // 0..7 -> rows seg*4 ..
        const int col = bc + c;
        const int ncl = min(col + RR, WW - 1) - max(col - RR, 0) + 1;
        const int r0 = seg * 4;

        float a0=0.f,a1=0.f,a3=0.f,a4=0.f,a5=0.f;
        #pragma unroll
        for (int d = 0; d < 9; ++d) {
            const int hb = (r0 + d) * PH2 + c;
            const uint2 fg = sFG[hb];
            const float2 f = __half22float2(u2h(fg.x));   // (h1, h4)
            const float2 g = __half22float2(u2h(fg.y));   // (h0, h3)
            a1 += f.x; a4 += f.y;
            a0 += g.x; a3 += g.y;
            a5 += __half2float(sK[hb]);
        }
        #pragma unroll
        for (int i = 0; i < 4; ++i) {
            const int gro = br + r0 + i;     // always < HH (512 = 16*32)
            {
                const int nr = min(gro + RR, HH - 1) - max(gro - RR, 0) + 1;
                const float Nf  = (float)(nr * ncl);
                const float den = fabsf(a4) + Nf * 1e-8f;
                const float Av  = __fdividef(a1, den);
                const float bv  = __fdividef(fmaf(-Av, a5, a3), a0);
                g_ABh[ibase + (size_t)gro * WW + col] = __floats2half2_rn(Av, bv);
            }
            if (i < 3) {
                const int ha = (r0 + 9 + i) * PH2 + c;
                const int hs = (r0 + i) * PH2 + c;
                const uint2 fga = sFG[ha], fgs = sFG[hs];
                const float2 fa = __half22float2(u2h(fga.x));
                const float2 fs = __half22float2(u2h(fgs.x));
                const float2 ga = __half22float2(u2h(fga.y));
                const float2 gs = __half22float2(u2h(fgs.y));
                a1 += fa.x - fs.x; a4 += fa.y - fs.y;
                a0 += ga.x - gs.x; a3 += ga.y - gs.y;
                a5 += __half2float(sK[ha]) - __half2float(sK[hs]);
            }
        }
    }
}

// ---------------- Stage 2: box filter (A,b) fp16 + final blend -----------------
__global__ __launch_bounds__(NTHR) void k_final(
    const float* __restrict__ X, float* __restrict__ out)
{
    __shared__ __half2 sABh[HR * PAB];      // (A, b) fp16
    __shared__ __half2 sHab[HR * PH2];      // h sums fp16

    const int tid = threadIdx.x;
    const int img = blockIdx.z;
    const int bc  = blockIdx.x * TC;
    const int br  = blockIdx.y * TR;
    const size_t ibase = (size_t)img * (HH * WW);

    // Phase A: uint4 = 4 pixels of half2 (A,b); 400 items
    #pragma unroll
    for (int it = 0; it < 2; ++it) {
        const int idx = tid + it * NTHR;
        if (idx < HR * (HC / 4)) {
            const int rh = idx / (HC / 4);
            const int vq = idx % (HC / 4);
            const int gr = br - RR + rh;
            const int gc = bc - RR + vq * 4;      // multiple of 4 -> 16B aligned
            uint4 v = make_uint4(0u, 0u, 0u, 0u);
            if (gr >= 0 && gr < HH && gc >= 0 && gc < WW) {
                const size_t o = ibase + (size_t)gr * WW + gc;
                v = *(const uint4*)(g_ABh + o);
            }
            const int sb = rh * PAB + vq * 4;
            sABh[sb+0] = u2h(v.x);
            sABh[sb+1] = u2h(v.y);
            sABh[sb+2] = u2h(v.z);
            sABh[sb+3] = u2h(v.w);
        }
    }
    __syncthreads();

    // Phase B: horizontal 9-tap, 4-col runs (rows 0..31 by 256 thr, 32..39 by 64)
    #pragma unroll
    for (int step = 0; step < 2; ++step) {
        int rh, cg;
        bool act;
        if (step == 0) { rh = tid & 31;          cg = tid >> 5; act = true; }
        else           { rh = 32 + (tid & 7);    cg = tid >> 3; act = (tid < 64); }
        if (act) {
            const int b2 = rh * PAB + cg * 4;
            const int hb = rh * PH2 + cg * 4;
            float hA = 0.f, hB = 0.f;
            #pragma unroll
            for (int d = 0; d < 9; ++d) {
                const float2 ab = __half22float2(sABh[b2 + d]);
                hA += ab.x; hB += ab.y;
            }
            sHab[hb] = __floats2half2_rn(hA, hB);
            #pragma unroll
            for (int s = 1; s < 4; ++s) {
                const float2 aa = __half22float2(sABh[b2 + 8 + s]);
                const float2 as = __half22float2(sABh[b2 + s - 1]);
                hA += aa.x - as.x;
                hB += aa.y - as.y;
                sHab[hb + s] = __floats2half2_rn(hA, hB);
            }
        }
    }
    __syncthreads();

    // Phase C: vertical 9-tap, 4-row runs, all 256 threads + blend
    {
        const int c   = tid & 31;
        const int seg = tid >> 5;
        const int col = bc + c;
        const int ncl = min(col + RR, WW - 1) - max(col - RR, 0) + 1;
        const int r0 = seg * 4;

        float xv[4];
        #pragma unroll
        for (int i = 0; i < 4; ++i)
            xv[i] = X[ibase + (size_t)(br + r0 + i) * WW + col];

        float aA = 0.f, aB = 0.f;
        #pragma unroll
        for (int d = 0; d < 9; ++d) {
            const float2 h = __half22float2(sHab[(r0 + d) * PH2 + c]);
            aA += h.x; aB += h.y;
        }
        #pragma unroll
        for (int i = 0; i < 4; ++i) {
            const int gro = br + r0 + i;     // always < HH
            const int nr = min(gro + RR, HH - 1) - max(gro - RR, 0) + 1;
            const float rcpN = __fdividef(1.f, (float)(nr * ncl));
            out[ibase + (size_t)gro * WW + col] = (aA * xv[i] + aB) * rcpN;
            if (i < 3) {
                const float2 ha = __half22float2(sHab[(r0 + 9 + i) * PH2 + c]);
                const float2 hs = __half22float2(sHab[(r0 + i) * PH2 + c]);
                aA += ha.x - hs.x;
                aB += ha.y - hs.y;
            }
        }
    }
}

extern "C" void kernel_launch(void* const* d_in, const int* in_sizes, int n_in,
                              void* d_out, int out_size) {
    const float* x = (const float*)d_in[0];  // lr_x
    const float* y = (const float*)d_in[1];  // lr_y
    const float* a = (const float*)d_in[2];  // l_a
    float* out = (float*)d_out;

    // smem: P 6560 + a 3360 + FG 10560 + K 2640 = 23120 B -> 8 blocks/SM (64 warps)
    const int smem_stats = HR * PP2 * 4 + HR * PINH * 2
                         + HR * PH2 * 8 + HR * PH2 * 2;
    cudaFuncSetAttribute(k_stats, cudaFuncAttributeMaxDynamicSharedMemorySize, smem_stats);

    dim3 grid(WW / TC, GY, NIMG);  // 16 x 16 x 64
    k_stats<<<grid, NTHR, smem_stats>>>(x, y, a);
    k_final<<<grid, NTHR>>>(x, out);
}